// round 1
// baseline (speedup 1.0000x reference)
#include <cuda_runtime.h>
#include <cuda_bf16.h>
#include <math.h>

// Problem constants
#define B_SZ 8
#define L_SZ 1024
#define DM 1024
#define NH 16
#define NG 4
#define HD 64
#define QKV_E 1536
#define MROWS (B_SZ * L_SZ)   // 8192

// ---------------- scratch (device globals; no allocation allowed) ----------
__device__ float g_qkv[MROWS * QKV_E];            // 50.3 MB
__device__ float g_q[B_SZ * NH * L_SZ * HD];      // 33.5 MB  [b,h,l,d]
__device__ float g_k[B_SZ * NG * L_SZ * HD];      // 8.4 MB   [b,g,l,d]
__device__ float g_v[B_SZ * NG * L_SZ * HD];      // 8.4 MB   [b,g,l,d]
__device__ float g_attn[MROWS * DM];              // 33.5 MB  [b,l, h*64+d]

// ============================================================================
// Kernel 1/4: C[M,N] = A[M,K] @ W[N,K]^T   (both row-major)
// 128x128 block tile, BK=16, 256 threads, 8x8 micro-tile.
// ============================================================================
__global__ void __launch_bounds__(256) sgemm_nt_kernel(
    const float* __restrict__ A, const float* __restrict__ W,
    float* __restrict__ C, int M, int N, int K)
{
    __shared__ float As[16][128];
    __shared__ float Ws[16][128];

    const int tid = threadIdx.x;
    const int tx = tid & 15;
    const int ty = tid >> 4;
    const int m0 = blockIdx.y * 128;
    const int n0 = blockIdx.x * 128;

    const int lr = tid >> 2;          // 0..63
    const int lc = (tid & 3) << 2;    // 0,4,8,12

    float acc[8][8];
#pragma unroll
    for (int i = 0; i < 8; i++)
#pragma unroll
        for (int j = 0; j < 8; j++) acc[i][j] = 0.f;

    const float* Aptr = A + (size_t)(m0 + lr) * K + lc;
    const float* Wptr = W + (size_t)(n0 + lr) * K + lc;

    for (int k0 = 0; k0 < K; k0 += 16) {
        float4 a0 = *(const float4*)(Aptr + k0);
        float4 a1 = *(const float4*)(Aptr + (size_t)64 * K + k0);
        float4 w0 = *(const float4*)(Wptr + k0);
        float4 w1 = *(const float4*)(Wptr + (size_t)64 * K + k0);
        __syncthreads();
        As[lc + 0][lr] = a0.x; As[lc + 1][lr] = a0.y;
        As[lc + 2][lr] = a0.z; As[lc + 3][lr] = a0.w;
        As[lc + 0][lr + 64] = a1.x; As[lc + 1][lr + 64] = a1.y;
        As[lc + 2][lr + 64] = a1.z; As[lc + 3][lr + 64] = a1.w;
        Ws[lc + 0][lr] = w0.x; Ws[lc + 1][lr] = w0.y;
        Ws[lc + 2][lr] = w0.z; Ws[lc + 3][lr] = w0.w;
        Ws[lc + 0][lr + 64] = w1.x; Ws[lc + 1][lr + 64] = w1.y;
        Ws[lc + 2][lr + 64] = w1.z; Ws[lc + 3][lr + 64] = w1.w;
        __syncthreads();
#pragma unroll
        for (int k = 0; k < 16; k++) {
            float4 af0 = *(const float4*)&As[k][ty * 8];
            float4 af1 = *(const float4*)&As[k][ty * 8 + 4];
            float4 wf0 = *(const float4*)&Ws[k][tx * 8];
            float4 wf1 = *(const float4*)&Ws[k][tx * 8 + 4];
            float a[8] = {af0.x, af0.y, af0.z, af0.w, af1.x, af1.y, af1.z, af1.w};
            float w[8] = {wf0.x, wf0.y, wf0.z, wf0.w, wf1.x, wf1.y, wf1.z, wf1.w};
#pragma unroll
            for (int i = 0; i < 8; i++)
#pragma unroll
                for (int j = 0; j < 8; j++)
                    acc[i][j] = fmaf(a[i], w[j], acc[i][j]);
        }
    }

#pragma unroll
    for (int i = 0; i < 8; i++) {
        float4 o0 = make_float4(acc[i][0], acc[i][1], acc[i][2], acc[i][3]);
        float4 o1 = make_float4(acc[i][4], acc[i][5], acc[i][6], acc[i][7]);
        float* Cp = C + (size_t)(m0 + ty * 8 + i) * N + n0 + tx * 8;
        *(float4*)(Cp) = o0;
        *(float4*)(Cp + 4) = o1;
    }
}

// ============================================================================
// Kernel 2: qk-norm + RoPE2D + scale(q) + transpose to [b,head,l,d]
// One warp per head-vector (64 dims); lane owns dims {2*lane, 2*lane+1}.
// ============================================================================
__global__ void __launch_bounds__(256) norm_rope_kernel(
    const float* __restrict__ qkv,
    float* __restrict__ qo, float* __restrict__ ko, float* __restrict__ vo)
{
    const int gwarp = (blockIdx.x * blockDim.x + threadIdx.x) >> 5;
    const int lane = threadIdx.x & 31;
    const int NVEC = MROWS * 24;
    if (gwarp >= NVEC) return;

    const int bl = gwarp / 24;
    const int slot = gwarp % 24;
    const int b = bl >> 10;
    const int l = bl & 1023;

    const float2 xv = *(const float2*)(qkv + (size_t)bl * QKV_E + slot * 64 + 2 * lane);
    float x1 = xv.x, x2 = xv.y;

    if (slot < 20) {
        // L2 norm over 64 dims
        float ss = x1 * x1 + x2 * x2;
#pragma unroll
        for (int o = 16; o > 0; o >>= 1)
            ss += __shfl_xor_sync(0xffffffffu, ss, o);
        float inv = 1.f / (sqrtf(ss) + 1e-10f);
        if (slot < 16) inv *= 0.125f;   // fold 1/sqrt(HD) into q
        x1 *= inv; x2 *= inv;

        // RoPE2D: freq = (h_idx + w_idx) * theta^(-2*lane/64)
        float psum = (float)((l >> 5) + (l & 31));
        float invfreq = exp2f(-0.41524101186098287f * (float)lane);
        float fr = psum * invfreq;
        float s, c;
        sincosf(fr, &s, &c);
        float olo = x1 * c - x2 * s;
        float ohi = x1 * s + x2 * c;

        float* dst;
        if (slot < 16)
            dst = qo + (((size_t)b * NH + slot) * L_SZ + l) * HD;
        else
            dst = ko + (((size_t)b * NG + (slot - 16)) * L_SZ + l) * HD;
        dst[lane] = olo;
        dst[lane + 32] = ohi;
    } else {
        float* dst = vo + (((size_t)b * NG + (slot - 20)) * L_SZ + l) * HD;
        *(float2*)(dst + 2 * lane) = xv;
    }
}

// ============================================================================
// Kernel 3: flash attention, fp32.
// Block = (qtile of 64 rows, head, batch), 256 threads.
// Qs/Ks stored d-major (transposed) for float4 fragment loads.
// ============================================================================
#define QPAD 68
__global__ void __launch_bounds__(256) attn_kernel(
    const float* __restrict__ Q, const float* __restrict__ Kt,
    const float* __restrict__ Vt, float* __restrict__ O)
{
    extern __shared__ float sm[];
    float* Qs = sm;                       // [64][QPAD] indexed [d][row]
    float* Ks = Qs + 64 * QPAD;           // [64][QPAD] indexed [d][kcol]
    float* Vs = Ks + 64 * QPAD;           // [64][64]   indexed [k][d]
    float* Ss = Vs + 64 * 64;             // [64][QPAD] indexed [row][k]
    float* mrow = Ss + 64 * QPAD;         // [64]
    float* lrow = mrow + 64;              // [64]
    float* rrow = lrow + 64;              // [64]

    const int qt = blockIdx.x;
    const int h = blockIdx.y;
    const int b = blockIdx.z;
    const int g = h >> 2;                 // GQA: head h -> group h/4

    const int tid = threadIdx.x;
    const int tx = tid & 15;
    const int ty = tid >> 4;

    const float* Qg = Q + (((size_t)b * NH + h) * L_SZ + qt * 64) * HD;
    const float* Kg = Kt + (((size_t)b * NG + g) * L_SZ) * HD;
    const float* Vg = Vt + (((size_t)b * NG + g) * L_SZ) * HD;

    // load Q tile transposed into Qs[d][row]
    {
        const int r = tid >> 2;
        const int d0 = (tid & 3) << 4;
#pragma unroll
        for (int c = 0; c < 16; c += 4) {
            float4 v = *(const float4*)(Qg + (size_t)r * HD + d0 + c);
            Qs[(d0 + c + 0) * QPAD + r] = v.x;
            Qs[(d0 + c + 1) * QPAD + r] = v.y;
            Qs[(d0 + c + 2) * QPAD + r] = v.z;
            Qs[(d0 + c + 3) * QPAD + r] = v.w;
        }
    }
    if (tid < 64) { mrow[tid] = -INFINITY; lrow[tid] = 0.f; }

    float acc[4][4];
#pragma unroll
    for (int i = 0; i < 4; i++)
#pragma unroll
        for (int j = 0; j < 4; j++) acc[i][j] = 0.f;

    for (int k0 = 0; k0 < L_SZ; k0 += 64) {
        __syncthreads();   // previous tile's PV reads of Ks/Vs/Ss are done
        // load K tile transposed, V tile natural
        {
            const int r = tid >> 2;
            const int d0 = (tid & 3) << 4;
#pragma unroll
            for (int c = 0; c < 16; c += 4) {
                float4 kv = *(const float4*)(Kg + (size_t)(k0 + r) * HD + d0 + c);
                Ks[(d0 + c + 0) * QPAD + r] = kv.x;
                Ks[(d0 + c + 1) * QPAD + r] = kv.y;
                Ks[(d0 + c + 2) * QPAD + r] = kv.z;
                Ks[(d0 + c + 3) * QPAD + r] = kv.w;
                float4 vv = *(const float4*)(Vg + (size_t)(k0 + r) * HD + d0 + c);
                *(float4*)(Vs + r * 64 + d0 + c) = vv;
            }
        }
        __syncthreads();

        // S = Q @ K^T  (scale already folded into Q)
        float s[4][4];
#pragma unroll
        for (int i = 0; i < 4; i++)
#pragma unroll
            for (int j = 0; j < 4; j++) s[i][j] = 0.f;
#pragma unroll
        for (int d = 0; d < 64; d++) {
            float4 qa = *(const float4*)(Qs + d * QPAD + ty * 4);
            float4 kb = *(const float4*)(Ks + d * QPAD + tx * 4);
            float av[4] = {qa.x, qa.y, qa.z, qa.w};
            float bv[4] = {kb.x, kb.y, kb.z, kb.w};
#pragma unroll
            for (int i = 0; i < 4; i++)
#pragma unroll
                for (int j = 0; j < 4; j++)
                    s[i][j] = fmaf(av[i], bv[j], s[i][j]);
        }
#pragma unroll
        for (int i = 0; i < 4; i++)
            *(float4*)(Ss + (ty * 4 + i) * QPAD + tx * 4) =
                make_float4(s[i][0], s[i][1], s[i][2], s[i][3]);
        __syncthreads();

        // online softmax: one thread per q-row
        if (tid < 64) {
            float m_old = mrow[tid];
            float mx = m_old;
            float* srow = Ss + tid * QPAD;
#pragma unroll 8
            for (int c = 0; c < 64; c++) mx = fmaxf(mx, srow[c]);
            float resc = __expf(m_old - mx);   // 0 on first tile (m_old=-inf)
            float sum = 0.f;
#pragma unroll 8
            for (int c = 0; c < 64; c++) {
                float p = __expf(srow[c] - mx);
                srow[c] = p;
                sum += p;
            }
            mrow[tid] = mx;
            lrow[tid] = lrow[tid] * resc + sum;
            rrow[tid] = resc;
        }
        __syncthreads();

        // rescale accumulators, then acc += P @ V
        float rf[4];
#pragma unroll
        for (int i = 0; i < 4; i++) rf[i] = rrow[ty * 4 + i];
#pragma unroll
        for (int i = 0; i < 4; i++)
#pragma unroll
            for (int j = 0; j < 4; j++) acc[i][j] *= rf[i];

#pragma unroll
        for (int k = 0; k < 64; k++) {
            float4 vb = *(const float4*)(Vs + k * 64 + tx * 4);
            float vv[4] = {vb.x, vb.y, vb.z, vb.w};
            float p0 = Ss[(ty * 4 + 0) * QPAD + k];
            float p1 = Ss[(ty * 4 + 1) * QPAD + k];
            float p2 = Ss[(ty * 4 + 2) * QPAD + k];
            float p3 = Ss[(ty * 4 + 3) * QPAD + k];
#pragma unroll
            for (int j = 0; j < 4; j++) {
                acc[0][j] = fmaf(p0, vv[j], acc[0][j]);
                acc[1][j] = fmaf(p1, vv[j], acc[1][j]);
                acc[2][j] = fmaf(p2, vv[j], acc[2][j]);
                acc[3][j] = fmaf(p3, vv[j], acc[3][j]);
            }
        }
    }

    // final normalize + write to [b, l, h*64+d]
#pragma unroll
    for (int i = 0; i < 4; i++) {
        int r = ty * 4 + i;
        float invl = 1.f / lrow[r];
        int q = qt * 64 + r;
        float4 o = make_float4(acc[i][0] * invl, acc[i][1] * invl,
                               acc[i][2] * invl, acc[i][3] * invl);
        *(float4*)(O + ((size_t)(b * L_SZ + q)) * DM + h * 64 + tx * 4) = o;
    }
}

// ============================================================================
// launch
// ============================================================================
extern "C" void kernel_launch(void* const* d_in, const int* in_sizes, int n_in,
                              void* d_out, int out_size)
{
    const float* x     = (const float*)d_in[0];   // [8,1024,1024]
    const float* w_qkv = (const float*)d_in[1];   // [1536,1024]
    const float* w_o   = (const float*)d_in[2];   // [1024,1024]
    float* out = (float*)d_out;

    float *qkv_p, *q_p, *k_p, *v_p, *attn_p;
    cudaGetSymbolAddress((void**)&qkv_p,  g_qkv);
    cudaGetSymbolAddress((void**)&q_p,    g_q);
    cudaGetSymbolAddress((void**)&k_p,    g_k);
    cudaGetSymbolAddress((void**)&v_p,    g_v);
    cudaGetSymbolAddress((void**)&attn_p, g_attn);

    // 1) QKV projection: [8192,1536] = x[8192,1024] @ w_qkv^T
    {
        dim3 grid(QKV_E / 128, MROWS / 128);
        sgemm_nt_kernel<<<grid, 256>>>(x, w_qkv, qkv_p, MROWS, QKV_E, DM);
    }

    // 2) norm + rope + transpose
    {
        int nvec = MROWS * 24;          // head-vectors
        int nwarps_per_blk = 8;
        int blocks = (nvec + nwarps_per_blk - 1) / nwarps_per_blk;
        norm_rope_kernel<<<blocks, 256>>>(qkv_p, q_p, k_p, v_p);
    }

    // 3) attention
    {
        int smem = (3 * 64 * QPAD + 64 * 64 + 3 * 64) * (int)sizeof(float);
        cudaFuncSetAttribute(attn_kernel,
                             cudaFuncAttributeMaxDynamicSharedMemorySize, smem);
        dim3 grid(L_SZ / 64, NH, B_SZ);
        attn_kernel<<<grid, 256, smem>>>(q_p, k_p, v_p, attn_p);
    }

    // 4) output projection: [8192,1024] = attn[8192,1024] @ w_o^T
    {
        dim3 grid(DM / 128, MROWS / 128);
        sgemm_nt_kernel<<<grid, 256>>>(attn_p, w_o, out, MROWS, DM, DM);
    }
}